// round 2
// baseline (speedup 1.0000x reference)
#include <cuda_runtime.h>

#define NCLS   2048
#define NROWS  32768
#define BLOCK  256
#define GRID   (NROWS / BLOCK)   // 128

__device__ double       g_sum   = 0.0;
__device__ unsigned int g_count = 0u;

__global__ __launch_bounds__(BLOCK) void mpl_fused(const float* __restrict__ x,
                                                   const int* __restrict__ tgt,
                                                   float* __restrict__ out) {
    __shared__ int    s_zero_rows[BLOCK];
    __shared__ int    s_zero_count;
    __shared__ float  s_warp[BLOCK / 32];

    const int tid  = threadIdx.x;
    const int lane = tid & 31;
    const int wid  = tid >> 5;

    if (tid == 0) s_zero_count = 0;
    __syncthreads();

    const int row = blockIdx.x * BLOCK + tid;
    const int t   = tgt[row];

    float local = 0.0f;
    if (t != 0) {
        // positive set = {1..C-1}; loss collapses to 2-class logistic:
        // loss = log(exp(x0) + exp(xt)) - xt
        const float x0 = __ldg(&x[(size_t)row * NCLS]);
        const float xt = __ldg(&x[(size_t)row * NCLS + t]);
        local = __logf(__expf(x0) + __expf(xt)) - xt;
    } else {
        const int slot = atomicAdd(&s_zero_count, 1);
        s_zero_rows[slot] = row;
    }
    __syncthreads();

    // Rare path (t==0): neg_sum + exp(x_t) == full-row sum of exps.
    double zacc = 0.0;                 // meaningful on (wid==0, lane==0) only
    const int nz = s_zero_count;
    for (int k = 0; k < nz; k++) {
        const int zrow = s_zero_rows[k];
        const float4* rp = reinterpret_cast<const float4*>(x + (size_t)zrow * NCLS);
        float s = 0.0f;
        #pragma unroll
        for (int j = tid; j < NCLS / 4; j += BLOCK) {
            const float4 v = __ldg(&rp[j]);
            s += __expf(v.x) + __expf(v.y) + __expf(v.z) + __expf(v.w);
        }
        #pragma unroll
        for (int off = 16; off > 0; off >>= 1)
            s += __shfl_down_sync(0xFFFFFFFFu, s, off);
        if (lane == 0) s_warp[wid] = s;
        __syncthreads();
        if (wid == 0) {
            float ws = (lane < BLOCK / 32) ? s_warp[lane] : 0.0f;
            #pragma unroll
            for (int off = 4; off > 0; off >>= 1)
                ws += __shfl_down_sync(0xFFFFFFFFu, ws, off);
            if (lane == 0) {
                const float x0 = __ldg(&x[(size_t)zrow * NCLS]);
                zacc += (double)(__logf(ws) - x0);
            }
        }
        __syncthreads();
    }

    // Block-level reduce of cheap-path losses
    float r = local;
    #pragma unroll
    for (int off = 16; off > 0; off >>= 1)
        r += __shfl_down_sync(0xFFFFFFFFu, r, off);
    if (lane == 0) s_warp[wid] = r;
    __syncthreads();

    // Grid-level: atomic accumulate + last-block finalize (no 2nd launch)
    if (tid == 0) {
        float bs = 0.0f;
        #pragma unroll
        for (int w = 0; w < BLOCK / 32; w++) bs += s_warp[w];
        atomicAdd(&g_sum, (double)bs + zacc);
        __threadfence();
        const unsigned int arrived = atomicAdd(&g_count, 1u);
        if (arrived == GRID - 1) {
            // all other blocks' g_sum adds are visible (fence + atomic order)
            const double total = atomicAdd(&g_sum, 0.0);   // coherent read
            out[0] = (float)(total / (double)NROWS);
            // reset device state so every graph replay is identical
            g_sum   = 0.0;
            __threadfence();
            g_count = 0u;
        }
    }
}

extern "C" void kernel_launch(void* const* d_in, const int* in_sizes, int n_in,
                              void* d_out, int out_size) {
    const float* x   = (const float*)d_in[0];
    const int*   tgt = (const int*)d_in[1];
    float*       out = (float*)d_out;

    mpl_fused<<<GRID, BLOCK>>>(x, tgt, out);
}